// round 13
// baseline (speedup 1.0000x reference)
#include <cuda_runtime.h>
#include <cuda_bf16.h>
#include <cuda_fp8.h>
#include <cstdint>

#define B_     8
#define C_     128
#define PIXPB  36864
#define NPIX   294912
#define NT     2304             // 128-pixel tiles
#define TPB    288              // tiles per batch
#define EPS    1e-6f
#define GRID_A 296
#define GRID_B 144              // 18 CTAs per batch x 16 tiles
#define SA     304              // bf16 A-tile row stride bytes (conflict-free)
#define SA8    144              // fp8 A-tile row stride bytes (conflict-free)
#define W1SCL  8.0f             // w1 pre-scale into e4m3 normal range

// ---------------- device globals (no allocation) ----------------
__device__ uint32_t g_s[(size_t)NPIX * 64];   // gated branch bf16x2 [pix][64]
__device__ float    g_gpart[NT * 128];        // per-tile GAP partials
__device__ float    g_att[B_ * C_];
// w1 fp8 frag image (pair-permuted, x8 scaled): [ks4][half][nbp8][lane][e4] u32 (4x e4m3)
__device__ uint32_t g_fw1 [4 * 2 * 8 * 32 * 4];
// bf16 pair-packed images: [ks8][(half)][nbp][lane][e4] u32 (bf16x2)
__device__ uint32_t g_fwf1[8 * 2 * 8 * 32 * 4];  // wf1 (pair-permuted), N=256
__device__ uint32_t g_fw2 [8 * 8 * 32 * 4];      // w2, N=128
__device__ uint32_t g_fwf2[8 * 8 * 32 * 4];      // wf2, N=128

__device__ __forceinline__ uint32_t pack_bf2(float a, float b) {
    __nv_bfloat162 h = __floats2bfloat162_rn(a, b);   // low = a
    return *reinterpret_cast<uint32_t*>(&h);
}
__device__ __forceinline__ float2 unpack_bf2(uint32_t w) {
    __nv_bfloat162 h = *reinterpret_cast<const __nv_bfloat162*>(&w);
    return make_float2(__low2float(h), __high2float(h));
}
__device__ __forceinline__ uint32_t pack_e4m3x4(float f0, float f1, float f2, float f3) {
    uint16_t lo, hi;
    asm("cvt.rn.satfinite.e4m3x2.f32 %0, %1, %2;" : "=h"(lo) : "f"(f1), "f"(f0));
    asm("cvt.rn.satfinite.e4m3x2.f32 %0, %1, %2;" : "=h"(hi) : "f"(f3), "f"(f2));
    uint32_t r; asm("mov.b32 %0, {%1, %2};" : "=r"(r) : "h"(lo), "h"(hi));
    return r;
}
__device__ __forceinline__ void mma_bf16(float* c, uint32_t a0, uint32_t a1,
                                         uint32_t a2, uint32_t a3,
                                         uint32_t b0, uint32_t b1) {
    asm volatile(
        "mma.sync.aligned.m16n8k16.row.col.f32.bf16.bf16.f32 "
        "{%0,%1,%2,%3}, {%4,%5,%6,%7}, {%8,%9}, {%0,%1,%2,%3};\n"
        : "+f"(c[0]), "+f"(c[1]), "+f"(c[2]), "+f"(c[3])
        : "r"(a0), "r"(a1), "r"(a2), "r"(a3), "r"(b0), "r"(b1));
}
__device__ __forceinline__ void mma_fp8(float* c, uint32_t a0, uint32_t a1,
                                        uint32_t a2, uint32_t a3,
                                        uint32_t b0, uint32_t b1) {
    asm volatile(
        "mma.sync.aligned.m16n8k32.row.col.f32.e4m3.e4m3.f32 "
        "{%0,%1,%2,%3}, {%4,%5,%6,%7}, {%8,%9}, {%0,%1,%2,%3};\n"
        : "+f"(c[0]), "+f"(c[1]), "+f"(c[2]), "+f"(c[3])
        : "r"(a0), "r"(a1), "r"(a2), "r"(a3), "r"(b0), "r"(b1));
}
__device__ __forceinline__ uint32_t smem_u32(const void* p) {
    uint32_t a;
    asm("{ .reg .u64 t; cvta.to.shared.u64 t, %1; cvt.u32.u64 %0, t; }" : "=r"(a) : "l"(p));
    return a;
}
#define CP_ASYNC16(dst, src) \
    asm volatile("cp.async.ca.shared.global [%0], [%1], 16;" :: "r"(dst), "l"(src))
#define CP_COMMIT()  asm volatile("cp.async.commit_group;" ::: "memory")
#define CP_WAIT1()   asm volatile("cp.async.wait_group 1;" ::: "memory")
#define CP_WAIT0()   asm volatile("cp.async.wait_group 0;" ::: "memory")

// =====================================================================
// k0: fragment images (unchanged from R12)
// =====================================================================
__global__ void k0_frags(const float* __restrict__ w1, const float* __restrict__ w2,
                         const float* __restrict__ wf1, const float* __restrict__ wf2)
{
    int i0 = blockIdx.x * blockDim.x + threadIdx.x, str = gridDim.x * blockDim.x;
    for (int i = i0; i < 8192; i += str) {
        int e4 = i & 3, lane = (i >> 2) & 31, nbp = (i >> 7) & 7;
        int half = (i >> 10) & 1, ks = i >> 11;
        int nbg = half * 16 + 2 * nbp + (e4 >> 1);
        int e = e4 & 1;
        int n = 8 * nbg + (lane >> 2);
        int k = 32 * ks + 4 * (lane & 3) + 16 * e;
        int o = (n >> 1) + (n & 1) * 128;
        uint32_t w = 0;
        #pragma unroll
        for (int j = 0; j < 4; ++j) {
            __nv_fp8_e4m3 v(w1[(k + j) * 256 + o] * W1SCL);
            w |= (uint32_t)(*reinterpret_cast<uint8_t*>(&v)) << (8 * j);
        }
        g_fw1[i] = w;
    }
    for (int i = i0; i < 16384; i += str) {
        int e4 = i & 3, lane = (i >> 2) & 31, nbp = (i >> 7) & 7;
        int half = (i >> 10) & 1, ks = i >> 11;
        int nbg = half * 16 + 2 * nbp + (e4 >> 1);
        int e = e4 & 1;
        int n = 8 * nbg + (lane >> 2);
        int k = 16 * ks + 2 * (lane & 3) + 8 * e;
        int o = (n >> 1) + (n & 1) * 128;
        g_fwf1[i] = pack_bf2(wf1[k * 256 + o], wf1[(k + 1) * 256 + o]);
    }
    for (int i = i0; i < 8192; i += str) {
        int e4 = i & 3, lane = (i >> 2) & 31, nbp = (i >> 7) & 7, ks = i >> 10;
        int nb = 2 * nbp + (e4 >> 1);
        int e = e4 & 1;
        int n = 8 * nb + (lane >> 2);
        int k = 16 * ks + 2 * (lane & 3) + 8 * e;
        g_fw2 [i] = pack_bf2(w2 [k * 128 + n], w2 [(k + 1) * 128 + n]);
        g_fwf2[i] = pack_bf2(wf2[k * 128 + n], wf2[(k + 1) * 128 + n]);
    }
}

// =====================================================================
// kA: (unchanged from R12 winner) fp8 w1 GEMM, 256 thr, 2 CTAs/SM.
// =====================================================================
#define KA_BT   18432
#define KA_FW1  (KA_BT + 38912)
#define KA_EW   (KA_FW1 + 32768)
#define KA_LN   (KA_EW + 2048)
#define KA_GAP  (KA_LN + 1024)
#define KA_SMEM (KA_GAP + 4096)

__global__ void __launch_bounds__(256, 2)
kA_spatial(const float* __restrict__ x,
           const float* __restrict__ ln1s, const float* __restrict__ ln1b,
           const float* __restrict__ b1,   const float* __restrict__ wdw,
           const float* __restrict__ bdw)
{
    extern __shared__ char sm[];
    const int tid = threadIdx.x, lane = tid & 31, warp = tid >> 5;
    const int q = lane & 3, r = lane >> 2, m0 = warp * 16;

    {
        uint4* dst = (uint4*)(sm + KA_FW1);
        const uint4* src = (const uint4*)g_fw1;
        for (int i = tid; i < 2048; i += 256) dst[i] = src[i];
        if (tid < 256) {
            int n = tid, o = (n >> 1) + (n & 1) * 128;
            float w = wdw[o];
            ((float2*)(sm + KA_EW))[n] = make_float2(w * (1.0f / W1SCL), b1[o] * w + bdw[o]);
        }
        if (tid < 128)
            ((float2*)(sm + KA_LN))[tid] = make_float2(ln1s[tid], ln1b[tid]);
    }
    __syncthreads();

    const float2* ewp = (const float2*)(sm + KA_EW);
    const float2* lnp = (const float2*)(sm + KA_LN);
    float* gapw = (float*)(sm + KA_GAP);
    const int pl = tid >> 1, h = tid & 1;

    for (int tile = blockIdx.x; tile < NT; tile += GRID_A) {
        const float4* xr = (const float4*)x + ((size_t)(tile * 128 + pl)) * 32 + h * 16;
        float4 xv[16];
        float s1 = 0.f, s2 = 0.f;
        #pragma unroll
        for (int i = 0; i < 16; ++i) {
            xv[i] = xr[i];
            s1 += xv[i].x + xv[i].y + xv[i].z + xv[i].w;
            s2 += xv[i].x*xv[i].x + xv[i].y*xv[i].y + xv[i].z*xv[i].z + xv[i].w*xv[i].w;
        }
        s1 += __shfl_xor_sync(0xffffffffu, s1, 1);
        s2 += __shfl_xor_sync(0xffffffffu, s2, 1);
        const float mu = s1 * (1.f/128.f);
        const float rs = rsqrtf(fmaxf(s2 * (1.f/128.f) - mu*mu, 0.f) + EPS);

        char* row8 = sm + pl * SA8 + h * 64;
        #pragma unroll
        for (int j = 0; j < 8; ++j) {
            float4 v0 = xv[2*j], v1 = xv[2*j+1];
            int c = h * 64 + 8 * j;
            float2 p0 = lnp[c],   p1 = lnp[c+1], p2 = lnp[c+2], p3 = lnp[c+3];
            float2 p4 = lnp[c+4], p5 = lnp[c+5], p6 = lnp[c+6], p7 = lnp[c+7];
            uint32_t w0 = pack_e4m3x4((v0.x-mu)*rs*p0.x+p0.y, (v0.y-mu)*rs*p1.x+p1.y,
                                      (v0.z-mu)*rs*p2.x+p2.y, (v0.w-mu)*rs*p3.x+p3.y);
            uint32_t w1w = pack_e4m3x4((v1.x-mu)*rs*p4.x+p4.y, (v1.y-mu)*rs*p5.x+p5.y,
                                       (v1.z-mu)*rs*p6.x+p6.y, (v1.w-mu)*rs*p7.x+p7.y);
            *(uint2*)(row8 + j * 8) = make_uint2(w0, w1w);
        }
        __syncwarp();

        const char* a8r = sm + (m0 + r) * SA8;
        uint32_t gsave[16];

        #pragma unroll 1
        for (int half = 0; half < 2; ++half) {
            float acc[16][4];
            #pragma unroll
            for (int nb = 0; nb < 16; ++nb)
                { acc[nb][0]=0.f; acc[nb][1]=0.f; acc[nb][2]=0.f; acc[nb][3]=0.f; }

            #pragma unroll 2
            for (int ks = 0; ks < 4; ++ks) {
                int kb = 32 * ks + 4 * q;
                uint32_t a0 = *(const uint32_t*)(a8r + kb);
                uint32_t a1 = *(const uint32_t*)(a8r + 8 * SA8 + kb);
                uint32_t a2 = *(const uint32_t*)(a8r + kb + 16);
                uint32_t a3 = *(const uint32_t*)(a8r + 8 * SA8 + kb + 16);
                const uint4* fb = (const uint4*)(sm + KA_FW1) + (ks * 2 + half) * 256 + lane;
                #pragma unroll
                for (int nbp = 0; nbp < 8; ++nbp) {
                    uint4 b = fb[nbp * 32];
                    mma_fp8(acc[2*nbp],   a0, a1, a2, a3, b.x, b.y);
                    mma_fp8(acc[2*nbp+1], a0, a1, a2, a3, b.z, b.w);
                }
            }

            #pragma unroll
            for (int nb = 0; nb < 16; ++nb) {
                int nbg = half * 16 + nb;
                int n0 = 8 * nbg + 2 * q, j = 4 * nbg + q;
                float2 e0 = ewp[n0], e1 = ewp[n0 + 1];
                float lo = (acc[nb][0]*e0.x + e0.y) * (acc[nb][1]*e1.x + e1.y);
                float hi = (acc[nb][2]*e0.x + e0.y) * (acc[nb][3]*e1.x + e1.y);
                float g = lo + hi;
                g += __shfl_xor_sync(0xffffffffu, g, 4);
                g += __shfl_xor_sync(0xffffffffu, g, 8);
                g += __shfl_xor_sync(0xffffffffu, g, 16);
                if (r == 0) gapw[warp * 128 + j] = g;
                if (half == 0) {
                    gsave[nb] = pack_bf2(lo, hi);
                } else {
                    *(__nv_bfloat16*)(sm + KA_BT + (m0 + r)     * SA + j * 2) = __float2bfloat16(lo);
                    *(__nv_bfloat16*)(sm + KA_BT + (m0 + r + 8) * SA + j * 2) = __float2bfloat16(hi);
                }
            }
            __syncwarp();
        }
        #pragma unroll
        for (int nb = 0; nb < 16; ++nb) {
            int j = 4 * nb + q;
            float2 v = unpack_bf2(gsave[nb]);
            *(__nv_bfloat16*)(sm + KA_BT + (m0 + r)     * SA + j * 2) = __float2bfloat16(v.x);
            *(__nv_bfloat16*)(sm + KA_BT + (m0 + r + 8) * SA + j * 2) = __float2bfloat16(v.y);
        }
        __syncwarp();

        #pragma unroll
        for (int i = 0; i < 8; ++i) {
            int u = lane + 32 * i, row = u >> 4, ch = u & 15;
            uint4 v = *(const uint4*)(sm + KA_BT + (m0 + row) * SA + ch * 16);
            ((uint4*)g_s)[((size_t)(tile * 128 + m0 + row)) * 16 + ch] = v;
        }

        __syncthreads();
        if (tid < 128) {
            float s = 0.f;
            #pragma unroll
            for (int w = 0; w < 8; ++w) s += gapw[w * 128 + tid];
            g_gpart[tile * 128 + tid] = s;
        }
        __syncthreads();
    }
}

// =====================================================================
// k2_se (unchanged)
// =====================================================================
__global__ void k2_se(const float* __restrict__ wse, const float* __restrict__ bse)
{
    __shared__ float red[4][128];
    __shared__ float gap[128];
    __shared__ float ps[4][128];
    const int b = blockIdx.x, tid = threadIdx.x;
    const int c = tid & 127, g = tid >> 7;

    float s = 0.f;
    const float* src = g_gpart + (size_t)(b * TPB + g * 72) * 128 + c;
    #pragma unroll 8
    for (int i = 0; i < 72; ++i) s += src[(size_t)i * 128];
    red[g][c] = s;
    __syncthreads();
    if (tid < 128)
        gap[tid] = ((red[0][tid] + red[1][tid]) + (red[2][tid] + red[3][tid])) * (1.f / PIXPB);
    __syncthreads();

    float a = 0.f;
    #pragma unroll 8
    for (int kk = 0; kk < 32; ++kk) {
        int k = 32 * g + kk;
        a += gap[k] * wse[k * 128 + c];
    }
    ps[g][c] = a;
    __syncthreads();
    if (tid < 128)
        g_att[b * 128 + tid] = bse[tid] +
            ((ps[0][tid] + ps[1][tid]) + (ps[2][tid] + ps[3][tid]));
}

// =====================================================================
// kB v2: 512 thr, 16 warps = (8 row-groups x 2 N-halves).
//     Per-warp work halves; 4 warps/SMSP. Cross-warp LN2 stats via smem.
// =====================================================================
#define KB_XM    38912
#define KB_FWF1  (KB_XM + 67584)
#define KB_FW2   (KB_FWF1 + 65536)
#define KB_E2    (KB_FW2 + 32768)
#define KB_ELN   (KB_E2 + 1024)
#define KB_EBF1  (KB_ELN + 1024)
#define KB_EGAM  (KB_EBF1 + 1024)
#define KB_ATT   (KB_EGAM + 1024)
#define KB_ST    (KB_ATT + 512)
#define KB_SMEM  (KB_ST + 2048)

__global__ void __launch_bounds__(512, 1)
kB_ffn(const float* __restrict__ x,
       const float* __restrict__ b2,   const float* __restrict__ beta,
       const float* __restrict__ ln2s, const float* __restrict__ ln2b,
       const float* __restrict__ bf1,  const float* __restrict__ bf2,
       const float* __restrict__ gamma, float* __restrict__ out)
{
    extern __shared__ char sm[];
    const int tid = threadIdx.x, lane = tid & 31, warp = tid >> 5;
    const int q = lane & 3, r = lane >> 2;
    const int rg = warp & 7, nh = warp >> 3, m0 = rg * 16;
    const uint32_t sm_base = smem_u32(sm);
    const int batch = blockIdx.x / 18, sub = blockIdx.x % 18;
    const int tbase = batch * TPB + sub;

    {
        uint4* d1 = (uint4*)(sm + KB_FWF1);
        const uint4* s1p = (const uint4*)g_fwf1;
        for (int i = tid; i < 4096; i += 512) d1[i] = s1p[i];
        uint4* d2 = (uint4*)(sm + KB_FW2);
        const uint4* s2p = (const uint4*)g_fw2;
        for (int i = tid; i < 2048; i += 512) d2[i] = s2p[i];
        if (tid < 128) {
            float be = beta[tid], ga = gamma[tid];
            ((float2*)(sm + KB_E2  ))[tid] = make_float2(be, be * b2[tid]);
            ((float2*)(sm + KB_ELN ))[tid] = make_float2(ln2s[tid], ln2b[tid]);
            ((float2*)(sm + KB_EGAM))[tid] = make_float2(ga, ga * bf2[tid]);
            ((float*)(sm + KB_ATT))[tid] = g_att[batch * 128 + tid];
        }
        if (tid < 256) {
            int n = tid, o = (n >> 1) + (n & 1) * 128;
            ((float*)(sm + KB_EBF1))[n] = bf1[o];
        }
    }
    __syncthreads();

    // scale staged w2 frags by att (pair-packed layout)
    {
        const float* attv = (const float*)(sm + KB_ATT);
        uint4* p = (uint4*)(sm + KB_FW2);
        for (int i = tid; i < 2048; i += 512) {
            int lane2 = i & 31, ks = i >> 8;
            int k0 = 16 * ks + 2 * (lane2 & 3);
            uint4 v = p[i];
            float2 w0 = unpack_bf2(v.x), w1v = unpack_bf2(v.y);
            float2 w2v = unpack_bf2(v.z), w3v = unpack_bf2(v.w);
            v.x = pack_bf2(w0.x  * attv[k0],     w0.y  * attv[k0 + 1]);
            v.y = pack_bf2(w1v.x * attv[k0 + 8], w1v.y * attv[k0 + 9]);
            v.z = pack_bf2(w2v.x * attv[k0],     w2v.y * attv[k0 + 1]);
            v.w = pack_bf2(w3v.x * attv[k0 + 8], w3v.y * attv[k0 + 9]);
            p[i] = v;
        }
    }
    __syncthreads();

    const float2* e2p  = (const float2*)(sm + KB_E2);
    const float2* elnp = (const float2*)(sm + KB_ELN);
    const float*  ebfp = (const float*)(sm + KB_EBF1);
    const float2* egap = (const float2*)(sm + KB_EGAM);
    float* xms = (float*)(sm + KB_XM);
    float* st  = (float*)(sm + KB_ST);
    const int pl4 = tid >> 2, qh = tid & 3;

    auto prefetch_s = [&](int t) {
        const char* sg = (const char*)(g_s + ((size_t)(t * 128 + pl4)) * 64) + qh * 64;
        uint32_t dst = sm_base + (uint32_t)pl4 * SA + qh * 64;
        #pragma unroll
        for (int j = 0; j < 4; ++j)
            CP_ASYNC16(dst + j * 16, sg + j * 16);
    };
    auto prefetch_x = [&](int t) {
        const float* xg = x + ((size_t)(t * 128 + pl4)) * 128 + qh * 32;
        uint32_t dst = sm_base + KB_XM + (uint32_t)pl4 * 528 + qh * 128;
        #pragma unroll
        for (int j = 0; j < 8; ++j)
            CP_ASYNC16(dst + j * 16, xg + j * 4);
    };

    prefetch_s(tbase); CP_COMMIT();
    prefetch_x(tbase); CP_COMMIT();

    #pragma unroll 1
    for (int it = 0; it < 16; ++it) {
        const int tile = tbase + 18 * it;
        const char* ar0 = sm + (m0 + r) * SA;

        CP_WAIT1();
        __syncthreads();                       // s tile fully staged

        // ---- GEMM w2 (att-folded), warp covers N-half nh ----
        float acc[8][4];
        #pragma unroll
        for (int nb = 0; nb < 8; ++nb)
            { acc[nb][0]=0.f; acc[nb][1]=0.f; acc[nb][2]=0.f; acc[nb][3]=0.f; }
        #pragma unroll 2
        for (int ks = 0; ks < 8; ++ks) {
            int kb = 32 * ks + 4 * q;
            uint32_t a0 = *(const uint32_t*)(ar0 + kb);
            uint32_t a1 = *(const uint32_t*)(ar0 + 8 * SA + kb);
            uint32_t a2 = *(const uint32_t*)(ar0 + kb + 16);
            uint32_t a3 = *(const uint32_t*)(ar0 + 8 * SA + kb + 16);
            const uint4* fb = (const uint4*)(sm + KB_FW2) + (ks * 8 + nh * 4) * 32 + lane;
            #pragma unroll
            for (int nbl = 0; nbl < 4; ++nbl) {
                uint4 b = fb[nbl * 32];
                mma_bf16(acc[2*nbl],   a0, a1, a2, a3, b.x, b.y);
                mma_bf16(acc[2*nbl+1], a0, a1, a2, a3, b.z, b.w);
            }
        }

        // ---- xm = x + beta*(d+b2) for warp's 64 channels; partial stats ----
        CP_WAIT0();
        __syncthreads();                       // x staged AND w2 A-reads done
        float s1a = 0.f, s2a = 0.f, s1b = 0.f, s2b = 0.f;
        #pragma unroll
        for (int ln = 0; ln < 8; ++ln) {
            int n0 = 64 * nh + 8 * ln + 2 * q;
            float2 e0 = e2p[n0], e1 = e2p[n0 + 1];
            float* pa = xms + (m0 + r)     * 132 + n0;
            float* pb = xms + (m0 + r + 8) * 132 + n0;
            float2 xa = *(float2*)pa;
            float2 xb = *(float2*)pb;
            float m00 = xa.x + acc[ln][0]*e0.x + e0.y;
            float m01 = xa.y + acc[ln][1]*e1.x + e1.y;
            float m10 = xb.x + acc[ln][2]*e0.x + e0.y;
            float m11 = xb.y + acc[ln][3]*e1.x + e1.y;
            *(float2*)pa = make_float2(m00, m01);
            *(float2*)pb = make_float2(m10, m11);
            s1a += m00 + m01; s2a += m00*m00 + m01*m01;
            s1b += m10 + m11; s2b += m10*m10 + m11*m11;
        }
        s1a += __shfl_xor_sync(0xffffffffu, s1a, 1); s1a += __shfl_xor_sync(0xffffffffu, s1a, 2);
        s2a += __shfl_xor_sync(0xffffffffu, s2a, 1); s2a += __shfl_xor_sync(0xffffffffu, s2a, 2);
        s1b += __shfl_xor_sync(0xffffffffu, s1b, 1); s1b += __shfl_xor_sync(0xffffffffu, s1b, 2);
        s2b += __shfl_xor_sync(0xffffffffu, s2b, 1); s2b += __shfl_xor_sync(0xffffffffu, s2b, 2);
        if (q == 0) {
            st[(m0 + r)     * 4 + 2 * nh]     = s1a;
            st[(m0 + r)     * 4 + 2 * nh + 1] = s2a;
            st[(m0 + r + 8) * 4 + 2 * nh]     = s1b;
            st[(m0 + r + 8) * 4 + 2 * nh + 1] = s2b;
        }
        __syncthreads();                       // stats visible

        const float fs1a = st[(m0 + r) * 4 + 0] + st[(m0 + r) * 4 + 2];
        const float fs2a = st[(m0 + r) * 4 + 1] + st[(m0 + r) * 4 + 3];
        const float fs1b = st[(m0 + r + 8) * 4 + 0] + st[(m0 + r + 8) * 4 + 2];
        const float fs2b = st[(m0 + r + 8) * 4 + 1] + st[(m0 + r + 8) * 4 + 3];
        const float mua = fs1a * (1.f/128.f);
        const float rsa = rsqrtf(fmaxf(fs2a * (1.f/128.f) - mua*mua, 0.f) + EPS);
        const float mub = fs1b * (1.f/128.f);
        const float rsb = rsqrtf(fmaxf(fs2b * (1.f/128.f) - mub*mub, 0.f) + EPS);

        // ---- A2 = LN2(xm) -> atile bf16 (warp's 64 channels) ----
        #pragma unroll
        for (int ln = 0; ln < 8; ++ln) {
            int n0 = 64 * nh + 8 * ln + 2 * q;
            float2 p0 = elnp[n0], p1 = elnp[n0 + 1];
            float2 va = *(const float2*)(xms + (m0 + r)     * 132 + n0);
            float2 vb = *(const float2*)(xms + (m0 + r + 8) * 132 + n0);
            *(uint32_t*)(sm + (m0 + r)     * SA + n0 * 2) =
                pack_bf2((va.x-mua)*rsa*p0.x+p0.y, (va.y-mua)*rsa*p1.x+p1.y);
            *(uint32_t*)(sm + (m0 + r + 8) * SA + n0 * 2) =
                pack_bf2((vb.x-mub)*rsb*p0.x+p0.y, (vb.y-mub)*rsb*p1.x+p1.y);
        }
        __syncthreads();                       // full atile = LN2(xm)

        // ---- GEMM wf1: both halves into regs (A loads shared per ks) ----
        float acc2[2][8][4];
        #pragma unroll
        for (int hf = 0; hf < 2; ++hf)
            #pragma unroll
            for (int nb = 0; nb < 8; ++nb)
                { acc2[hf][nb][0]=0.f; acc2[hf][nb][1]=0.f; acc2[hf][nb][2]=0.f; acc2[hf][nb][3]=0.f; }
        #pragma unroll 2
        for (int ks = 0; ks < 8; ++ks) {
            int kb = 32 * ks + 4 * q;
            uint32_t a0 = *(const uint32_t*)(ar0 + kb);
            uint32_t a1 = *(const uint32_t*)(ar0 + 8 * SA + kb);
            uint32_t a2 = *(const uint32_t*)(ar0 + kb + 16);
            uint32_t a3 = *(const uint32_t*)(ar0 + 8 * SA + kb + 16);
            const uint4* fb = (const uint4*)(sm + KB_FWF1) + (ks * 16 + nh * 4) * 32 + lane;
            #pragma unroll
            for (int hf = 0; hf < 2; ++hf) {
                const uint4* fh = fb + hf * 256;    // half stride = 8*32 uint4
                #pragma unroll
                for (int nbl = 0; nbl < 4; ++nbl) {
                    uint4 b = fh[nbl * 32];
                    mma_bf16(acc2[hf][2*nbl],   a0, a1, a2, a3, b.x, b.y);
                    mma_bf16(acc2[hf][2*nbl+1], a0, a1, a2, a3, b.z, b.w);
                }
            }
        }
        __syncthreads();                       // all wf1 A-reads done

        // ---- gate -> atile bf16 ----
        #pragma unroll
        for (int hf = 0; hf < 2; ++hf) {
            #pragma unroll
            for (int ln = 0; ln < 8; ++ln) {
                int nbg = hf * 16 + nh * 8 + ln;
                int n0g = 8 * nbg + 2 * q, j = 4 * nbg + q;
                float e0 = ebfp[n0g], e1 = ebfp[n0g + 1];
                float lo = (acc2[hf][ln][0] + e0) * (acc2[hf][ln][1] + e1);
                float hi = (acc2[hf][ln][2] + e0) * (acc2[hf][ln][3] + e1);
                *(__nv_bfloat16*)(sm + (m0 + r)     * SA + j * 2) = __float2bfloat16(lo);
                *(__nv_bfloat16*)(sm + (m0 + r + 8) * SA + j * 2) = __float2bfloat16(hi);
            }
        }
        __syncthreads();                       // full gate tile

        // ---- GEMM wf2 (frags via LDG.128) ----
        float acc3[8][4];
        #pragma unroll
        for (int nb = 0; nb < 8; ++nb)
            { acc3[nb][0]=0.f; acc3[nb][1]=0.f; acc3[nb][2]=0.f; acc3[nb][3]=0.f; }
        #pragma unroll 2
        for (int ks = 0; ks < 8; ++ks) {
            int kb = 32 * ks + 4 * q;
            uint32_t a0 = *(const uint32_t*)(ar0 + kb);
            uint32_t a1 = *(const uint32_t*)(ar0 + 8 * SA + kb);
            uint32_t a2 = *(const uint32_t*)(ar0 + kb + 16);
            uint32_t a3 = *(const uint32_t*)(ar0 + 8 * SA + kb + 16);
            const uint4* fb = (const uint4*)g_fwf2 + (ks * 8 + nh * 4) * 32 + lane;
            #pragma unroll
            for (int nbl = 0; nbl < 4; ++nbl) {
                uint4 b = __ldg(fb + nbl * 32);
                mma_bf16(acc3[2*nbl],   a0, a1, a2, a3, b.x, b.y);
                mma_bf16(acc3[2*nbl+1], a0, a1, a2, a3, b.z, b.w);
            }
        }
        __syncthreads();                       // wf2 A-reads done -> atile reusable

        if (it < 15) { prefetch_s(tile + 18); CP_COMMIT(); }

        // ---- out = xm + gamma*(d+bf2) (warp's channels) ----
        float* or0 = out + ((size_t)(tile * 128 + m0 + r)) * 128;
        float* or8 = or0 + (size_t)8 * 128;
        #pragma unroll
        for (int ln = 0; ln < 8; ++ln) {
            int n0 = 64 * nh + 8 * ln + 2 * q;
            float2 g0 = egap[n0], g1 = egap[n0 + 1];
            float2 va = *(const float2*)(xms + (m0 + r)     * 132 + n0);
            float2 vb = *(const float2*)(xms + (m0 + r + 8) * 132 + n0);
            *(float2*)(or0 + n0) = make_float2(va.x + acc3[ln][0]*g0.x + g0.y,
                                               va.y + acc3[ln][1]*g1.x + g1.y);
            *(float2*)(or8 + n0) = make_float2(vb.x + acc3[ln][2]*g0.x + g0.y,
                                               vb.y + acc3[ln][3]*g1.x + g1.y);
        }
        __syncthreads();                       // xm reads done -> xm region reusable

        if (it < 15) { prefetch_x(tile + 18); CP_COMMIT(); }
    }
}

// =====================================================================
// launch
// =====================================================================
extern "C" void kernel_launch(void* const* d_in, const int* in_sizes, int n_in,
                              void* d_out, int out_size)
{
    (void)in_sizes; (void)n_in; (void)out_size;
    const float* x     = (const float*)d_in[0];
    const float* ln1s  = (const float*)d_in[1];
    const float* ln1b  = (const float*)d_in[2];
    const float* w1    = (const float*)d_in[3];
    const float* b1    = (const float*)d_in[4];
    const float* wdw   = (const float*)d_in[5];
    const float* bdw   = (const float*)d_in[6];
    const float* wse   = (const float*)d_in[7];
    const float* bse   = (const float*)d_in[8];
    const float* w2    = (const float*)d_in[9];
    const float* b2    = (const float*)d_in[10];
    const float* ln2s  = (const float*)d_in[11];
    const float* ln2b  = (const float*)d_in[12];
    const float* wf1   = (const float*)d_in[13];
    const float* bf1   = (const float*)d_in[14];
    const float* wf2   = (const float*)d_in[15];
    const float* bf2   = (const float*)d_in[16];
    const float* beta  = (const float*)d_in[17];
    const float* gamma = (const float*)d_in[18];
    float* out = (float*)d_out;

    cudaFuncSetAttribute(kA_spatial, cudaFuncAttributeMaxDynamicSharedMemorySize, KA_SMEM);
    cudaFuncSetAttribute(kB_ffn,     cudaFuncAttributeMaxDynamicSharedMemorySize, KB_SMEM);

    k0_frags<<<64, 256>>>(w1, w2, wf1, wf2);
    kA_spatial<<<GRID_A, 256, KA_SMEM>>>(x, ln1s, ln1b, b1, wdw, bdw);
    k2_se<<<B_, 512>>>(wse, bse);
    kB_ffn<<<GRID_B, 512, KB_SMEM>>>(x, b2, beta, ln2s, ln2b, bf1, bf2, gamma, out);
}

// round 14
// speedup vs baseline: 1.2524x; 1.2524x over previous
#include <cuda_runtime.h>
#include <cuda_bf16.h>
#include <cuda_fp8.h>
#include <cstdint>

#define B_     8
#define C_     128
#define PIXPB  36864
#define NPIX   294912
#define NT     2304             // 128-pixel tiles
#define TPB    288              // tiles per batch
#define EPS    1e-6f
#define GRID_A 296
#define GRID_B 144              // 18 CTAs per batch x 16 tiles
#define SA     304              // bf16 A-tile row stride bytes (conflict-free)
#define SA8    144              // fp8 A-tile row stride bytes (conflict-free)
#define W1SCL  8.0f             // w1 pre-scale into e4m3 normal range
#define W2SCL  64.0f            // w2 pre-scale
#define SSCL   256.0f           // s pre-scale for e4m3 storage

// ---------------- device globals (no allocation) ----------------
__device__ uint8_t  g_s8[(size_t)NPIX * 128]; // gated branch, e4m3 x SSCL, [pix][128]
__device__ float    g_gpart[NT * 128];        // per-tile GAP partials
__device__ float    g_att[B_ * C_];
// w1 fp8 frag image (pair-permuted, x8): [ks4][half][nbp8][lane][e4] u32 (4x e4m3)
__device__ uint32_t g_fw1 [4 * 2 * 8 * 32 * 4];
// w2 fp8 frag image (x64): [ks4][nbp8][lane][e4] u32 (4x e4m3)
__device__ uint32_t g_fw2f[4 * 8 * 32 * 4];
// bf16 pair-packed images: [ks8][(half)][nbp][lane][e4] u32 (bf16x2)
__device__ uint32_t g_fwf1[8 * 2 * 8 * 32 * 4];  // wf1 (pair-permuted), N=256
__device__ uint32_t g_fwf2[8 * 8 * 32 * 4];      // wf2, N=128

__device__ __forceinline__ uint32_t pack_bf2(float a, float b) {
    __nv_bfloat162 h = __floats2bfloat162_rn(a, b);   // low = a
    return *reinterpret_cast<uint32_t*>(&h);
}
__device__ __forceinline__ float2 unpack_bf2(uint32_t w) {
    __nv_bfloat162 h = *reinterpret_cast<const __nv_bfloat162*>(&w);
    return make_float2(__low2float(h), __high2float(h));
}
__device__ __forceinline__ uint32_t pack_e4m3x4(float f0, float f1, float f2, float f3) {
    uint16_t lo, hi;
    asm("cvt.rn.satfinite.e4m3x2.f32 %0, %1, %2;" : "=h"(lo) : "f"(f1), "f"(f0));
    asm("cvt.rn.satfinite.e4m3x2.f32 %0, %1, %2;" : "=h"(hi) : "f"(f3), "f"(f2));
    uint32_t r; asm("mov.b32 %0, {%1, %2};" : "=r"(r) : "h"(lo), "h"(hi));
    return r;
}
__device__ __forceinline__ uint8_t f2e4m3(float f) {
    __nv_fp8_e4m3 v(f);
    return *reinterpret_cast<uint8_t*>(&v);
}
__device__ __forceinline__ float e4m3f(uint8_t b) {
    __nv_fp8_e4m3 v = *reinterpret_cast<__nv_fp8_e4m3*>(&b);
    return float(v);
}
__device__ __forceinline__ void mma_bf16(float* c, uint32_t a0, uint32_t a1,
                                         uint32_t a2, uint32_t a3,
                                         uint32_t b0, uint32_t b1) {
    asm volatile(
        "mma.sync.aligned.m16n8k16.row.col.f32.bf16.bf16.f32 "
        "{%0,%1,%2,%3}, {%4,%5,%6,%7}, {%8,%9}, {%0,%1,%2,%3};\n"
        : "+f"(c[0]), "+f"(c[1]), "+f"(c[2]), "+f"(c[3])
        : "r"(a0), "r"(a1), "r"(a2), "r"(a3), "r"(b0), "r"(b1));
}
__device__ __forceinline__ void mma_fp8(float* c, uint32_t a0, uint32_t a1,
                                        uint32_t a2, uint32_t a3,
                                        uint32_t b0, uint32_t b1) {
    asm volatile(
        "mma.sync.aligned.m16n8k32.row.col.f32.e4m3.e4m3.f32 "
        "{%0,%1,%2,%3}, {%4,%5,%6,%7}, {%8,%9}, {%0,%1,%2,%3};\n"
        : "+f"(c[0]), "+f"(c[1]), "+f"(c[2]), "+f"(c[3])
        : "r"(a0), "r"(a1), "r"(a2), "r"(a3), "r"(b0), "r"(b1));
}
__device__ __forceinline__ uint32_t smem_u32(const void* p) {
    uint32_t a;
    asm("{ .reg .u64 t; cvta.to.shared.u64 t, %1; cvt.u32.u64 %0, t; }" : "=r"(a) : "l"(p));
    return a;
}
#define CP_ASYNC16(dst, src) \
    asm volatile("cp.async.ca.shared.global [%0], [%1], 16;" :: "r"(dst), "l"(src))
#define CP_COMMIT()  asm volatile("cp.async.commit_group;" ::: "memory")
#define CP_WAIT1()   asm volatile("cp.async.wait_group 1;" ::: "memory")
#define CP_WAIT0()   asm volatile("cp.async.wait_group 0;" ::: "memory")

// =====================================================================
// k0: fragment images.
// fp8 m16n8k32 col-B frag: lane holds B[k..k+3][n], n = 8nb + lane/4,
//   k = 32ks + 4*(lane%4) + 16e.  bf16 m16n8k16: k = 16ks + 2*(lane%4) + 8e.
// w1/wf1 pair-permuted: img col n -> orig col (n>>1)+(n&1)*128
// =====================================================================
__global__ void k0_frags(const float* __restrict__ w1, const float* __restrict__ w2,
                         const float* __restrict__ wf1, const float* __restrict__ wf2)
{
    int i0 = blockIdx.x * blockDim.x + threadIdx.x, str = gridDim.x * blockDim.x;
    // w1 fp8 image: 8192 words
    for (int i = i0; i < 8192; i += str) {
        int e4 = i & 3, lane = (i >> 2) & 31, nbp = (i >> 7) & 7;
        int half = (i >> 10) & 1, ks = i >> 11;
        int nbg = half * 16 + 2 * nbp + (e4 >> 1);
        int e = e4 & 1;
        int n = 8 * nbg + (lane >> 2);
        int k = 32 * ks + 4 * (lane & 3) + 16 * e;
        int o = (n >> 1) + (n & 1) * 128;
        uint32_t w = 0;
        #pragma unroll
        for (int j = 0; j < 4; ++j)
            w |= (uint32_t)f2e4m3(w1[(k + j) * 256 + o] * W1SCL) << (8 * j);
        g_fw1[i] = w;
    }
    // w2 fp8 image: 4096 words
    for (int i = i0; i < 4096; i += str) {
        int e4 = i & 3, lane = (i >> 2) & 31, nbp = (i >> 7) & 7, ks = i >> 10;
        int nb = 2 * nbp + (e4 >> 1);
        int e = e4 & 1;
        int n = 8 * nb + (lane >> 2);
        int k = 32 * ks + 4 * (lane & 3) + 16 * e;
        uint32_t w = 0;
        #pragma unroll
        for (int j = 0; j < 4; ++j)
            w |= (uint32_t)f2e4m3(w2[(k + j) * 128 + n] * W2SCL) << (8 * j);
        g_fw2f[i] = w;
    }
    // wf1 bf16 image: 16384 words
    for (int i = i0; i < 16384; i += str) {
        int e4 = i & 3, lane = (i >> 2) & 31, nbp = (i >> 7) & 7;
        int half = (i >> 10) & 1, ks = i >> 11;
        int nbg = half * 16 + 2 * nbp + (e4 >> 1);
        int e = e4 & 1;
        int n = 8 * nbg + (lane >> 2);
        int k = 16 * ks + 2 * (lane & 3) + 8 * e;
        int o = (n >> 1) + (n & 1) * 128;
        g_fwf1[i] = pack_bf2(wf1[k * 256 + o], wf1[(k + 1) * 256 + o]);
    }
    // wf2 bf16 image: 8192 words
    for (int i = i0; i < 8192; i += str) {
        int e4 = i & 3, lane = (i >> 2) & 31, nbp = (i >> 7) & 7, ks = i >> 10;
        int nb = 2 * nbp + (e4 >> 1);
        int e = e4 & 1;
        int n = 8 * nb + (lane >> 2);
        int k = 16 * ks + 2 * (lane & 3) + 8 * e;
        g_fwf2[i] = pack_bf2(wf2[k * 128 + n], wf2[(k + 1) * 128 + n]);
    }
}

// =====================================================================
// kA: 256 thr, 8 warps x 16 rows, 2 CTAs/SM.
//     LN1 (fp8 A) -> fp8 mma(w1, 2 x n128) -> dw-affine + gate
//     -> g_s8 (e4m3 x SSCL, written into dead A-region) + per-tile GAP.
// =====================================================================
#define KA_FW1  18432
#define KA_EW   (KA_FW1 + 32768)
#define KA_LN   (KA_EW + 2048)
#define KA_GAP  (KA_LN + 1024)
#define KA_SMEM (KA_GAP + 4096)   // 58368

__global__ void __launch_bounds__(256, 2)
kA_spatial(const float* __restrict__ x,
           const float* __restrict__ ln1s, const float* __restrict__ ln1b,
           const float* __restrict__ b1,   const float* __restrict__ wdw,
           const float* __restrict__ bdw)
{
    extern __shared__ char sm[];
    const int tid = threadIdx.x, lane = tid & 31, warp = tid >> 5;
    const int q = lane & 3, r = lane >> 2, m0 = warp * 16;

    {
        uint4* dst = (uint4*)(sm + KA_FW1);
        const uint4* src = (const uint4*)g_fw1;
        for (int i = tid; i < 2048; i += 256) dst[i] = src[i];
        if (tid < 256) {
            int n = tid, o = (n >> 1) + (n & 1) * 128;
            float w = wdw[o];
            ((float2*)(sm + KA_EW))[n] = make_float2(w * (1.0f / W1SCL), b1[o] * w + bdw[o]);
        }
        if (tid < 128)
            ((float2*)(sm + KA_LN))[tid] = make_float2(ln1s[tid], ln1b[tid]);
    }
    __syncthreads();

    const float2* ewp = (const float2*)(sm + KA_EW);
    const float2* lnp = (const float2*)(sm + KA_LN);
    float* gapw = (float*)(sm + KA_GAP);
    const int pl = tid >> 1, h = tid & 1;

    for (int tile = blockIdx.x; tile < NT; tile += GRID_A) {
        // ---- LN1: thread = (pixel pl, channel half h) -> fp8 A-tile ----
        const float4* xr = (const float4*)x + ((size_t)(tile * 128 + pl)) * 32 + h * 16;
        float4 xv[16];
        float s1 = 0.f, s2 = 0.f;
        #pragma unroll
        for (int i = 0; i < 16; ++i) {
            xv[i] = xr[i];
            s1 += xv[i].x + xv[i].y + xv[i].z + xv[i].w;
            s2 += xv[i].x*xv[i].x + xv[i].y*xv[i].y + xv[i].z*xv[i].z + xv[i].w*xv[i].w;
        }
        s1 += __shfl_xor_sync(0xffffffffu, s1, 1);
        s2 += __shfl_xor_sync(0xffffffffu, s2, 1);
        const float mu = s1 * (1.f/128.f);
        const float rs = rsqrtf(fmaxf(s2 * (1.f/128.f) - mu*mu, 0.f) + EPS);

        char* row8 = sm + pl * SA8 + h * 64;
        #pragma unroll
        for (int j = 0; j < 8; ++j) {
            float4 v0 = xv[2*j], v1 = xv[2*j+1];
            int c = h * 64 + 8 * j;
            float2 p0 = lnp[c],   p1 = lnp[c+1], p2 = lnp[c+2], p3 = lnp[c+3];
            float2 p4 = lnp[c+4], p5 = lnp[c+5], p6 = lnp[c+6], p7 = lnp[c+7];
            uint32_t w0 = pack_e4m3x4((v0.x-mu)*rs*p0.x+p0.y, (v0.y-mu)*rs*p1.x+p1.y,
                                      (v0.z-mu)*rs*p2.x+p2.y, (v0.w-mu)*rs*p3.x+p3.y);
            uint32_t w1w = pack_e4m3x4((v1.x-mu)*rs*p4.x+p4.y, (v1.y-mu)*rs*p5.x+p5.y,
                                       (v1.z-mu)*rs*p6.x+p6.y, (v1.w-mu)*rs*p7.x+p7.y);
            *(uint2*)(row8 + j * 8) = make_uint2(w0, w1w);
        }
        __syncwarp();

        const char* a8r = sm + (m0 + r) * SA8;
        uint32_t gsave[16];

        #pragma unroll 1
        for (int half = 0; half < 2; ++half) {
            float acc[16][4];
            #pragma unroll
            for (int nb = 0; nb < 16; ++nb)
                { acc[nb][0]=0.f; acc[nb][1]=0.f; acc[nb][2]=0.f; acc[nb][3]=0.f; }

            #pragma unroll 2
            for (int ks = 0; ks < 4; ++ks) {
                int kb = 32 * ks + 4 * q;
                uint32_t a0 = *(const uint32_t*)(a8r + kb);
                uint32_t a1 = *(const uint32_t*)(a8r + 8 * SA8 + kb);
                uint32_t a2 = *(const uint32_t*)(a8r + kb + 16);
                uint32_t a3 = *(const uint32_t*)(a8r + 8 * SA8 + kb + 16);
                const uint4* fb = (const uint4*)(sm + KA_FW1) + (ks * 2 + half) * 256 + lane;
                #pragma unroll
                for (int nbp = 0; nbp < 8; ++nbp) {
                    uint4 b = fb[nbp * 32];
                    mma_fp8(acc[2*nbp],   a0, a1, a2, a3, b.x, b.y);
                    mma_fp8(acc[2*nbp+1], a0, a1, a2, a3, b.z, b.w);
                }
            }

            #pragma unroll
            for (int nb = 0; nb < 16; ++nb) {
                int nbg = half * 16 + nb;
                int n0 = 8 * nbg + 2 * q, j = 4 * nbg + q;
                float2 e0 = ewp[n0], e1 = ewp[n0 + 1];
                float lo = (acc[nb][0]*e0.x + e0.y) * (acc[nb][1]*e1.x + e1.y);
                float hi = (acc[nb][2]*e0.x + e0.y) * (acc[nb][3]*e1.x + e1.y);
                float g = lo + hi;
                g += __shfl_xor_sync(0xffffffffu, g, 4);
                g += __shfl_xor_sync(0xffffffffu, g, 8);
                g += __shfl_xor_sync(0xffffffffu, g, 16);
                if (r == 0) gapw[warp * 128 + j] = g;
                if (half == 0) {
                    gsave[nb] = pack_bf2(lo, hi);     // park: A-region still live for half-1 GEMM
                } else {
                    // half-1 GEMM already consumed the A-region: write s fp8 in place
                    *(uint8_t*)(sm + (m0 + r)     * SA8 + j) = f2e4m3(lo * SSCL);
                    *(uint8_t*)(sm + (m0 + r + 8) * SA8 + j) = f2e4m3(hi * SSCL);
                }
            }
            __syncwarp();
        }
        #pragma unroll
        for (int nb = 0; nb < 16; ++nb) {
            int j = 4 * nb + q;
            float2 v = unpack_bf2(gsave[nb]);
            *(uint8_t*)(sm + (m0 + r)     * SA8 + j) = f2e4m3(v.x * SSCL);
            *(uint8_t*)(sm + (m0 + r + 8) * SA8 + j) = f2e4m3(v.y * SSCL);
        }
        __syncwarp();

        // ---- coalesced copy to g_s8 (warp-local 16 rows x 128B) ----
        #pragma unroll
        for (int i = 0; i < 4; ++i) {
            int u = lane + 32 * i, row = u >> 3, ch = u & 7;
            uint4 v = *(const uint4*)(sm + (m0 + row) * SA8 + ch * 16);
            ((uint4*)g_s8)[((size_t)(tile * 128 + m0 + row)) * 8 + ch] = v;
        }

        // ---- GAP partial: sum 8 warps in fixed order ----
        __syncthreads();
        if (tid < 128) {
            float s = 0.f;
            #pragma unroll
            for (int w = 0; w < 8; ++w) s += gapw[w * 128 + tid];
            g_gpart[tile * 128 + tid] = s;
        }
        __syncthreads();
    }
}

// =====================================================================
// k2_se: merged GAP reduce + SE matvec (unchanged)
// =====================================================================
__global__ void k2_se(const float* __restrict__ wse, const float* __restrict__ bse)
{
    __shared__ float red[4][128];
    __shared__ float gap[128];
    __shared__ float ps[4][128];
    const int b = blockIdx.x, tid = threadIdx.x;
    const int c = tid & 127, g = tid >> 7;

    float s = 0.f;
    const float* src = g_gpart + (size_t)(b * TPB + g * 72) * 128 + c;
    #pragma unroll 8
    for (int i = 0; i < 72; ++i) s += src[(size_t)i * 128];
    red[g][c] = s;
    __syncthreads();
    if (tid < 128)
        gap[tid] = ((red[0][tid] + red[1][tid]) + (red[2][tid] + red[3][tid])) * (1.f / PIXPB);
    __syncthreads();

    float a = 0.f;
    #pragma unroll 8
    for (int kk = 0; kk < 32; ++kk) {
        int k = 32 * g + kk;
        a += gap[k] * wse[k * 128 + c];
    }
    ps[g][c] = a;
    __syncthreads();
    if (tid < 128)
        g_att[b * 128 + tid] = bse[tid] +
            ((ps[0][tid] + ps[1][tid]) + (ps[2][tid] + ps[3][tid]));
}

// =====================================================================
// kB: R12 structure (256 thr, 8 warps x 16 rows, batch-fixed CTAs),
//     w2 GEMM now fp8 (A = s fp8, B = w2*att fp8), scale folded in beta.
// =====================================================================
#define KB_XM    38912
#define KB_FWF1  (KB_XM + 67584)
#define KB_FW2F  (KB_FWF1 + 65536)
#define KB_S8    (KB_FW2F + 16384)
#define KB_E2    (KB_S8 + 18432)
#define KB_ELN   (KB_E2 + 1024)
#define KB_EBF1  (KB_ELN + 1024)
#define KB_EGAM  (KB_EBF1 + 1024)
#define KB_ATT   (KB_EGAM + 1024)
#define KB_SMEM  (KB_ATT + 512)     // 211456

__global__ void __launch_bounds__(256, 1)
kB_ffn(const float* __restrict__ x,
       const float* __restrict__ b2,   const float* __restrict__ beta,
       const float* __restrict__ ln2s, const float* __restrict__ ln2b,
       const float* __restrict__ bf1,  const float* __restrict__ bf2,
       const float* __restrict__ gamma, float* __restrict__ out)
{
    extern __shared__ char sm[];
    const int tid = threadIdx.x, lane = tid & 31, warp = tid >> 5;
    const int q = lane & 3, r = lane >> 2, m0 = warp * 16;
    const uint32_t sm_base = smem_u32(sm);
    const int batch = blockIdx.x / 18, sub = blockIdx.x % 18;
    const int tbase = batch * TPB + sub;

    {
        uint4* d1 = (uint4*)(sm + KB_FWF1);
        const uint4* s1p = (const uint4*)g_fwf1;
        for (int i = tid; i < 4096; i += 256) d1[i] = s1p[i];
        uint4* d2 = (uint4*)(sm + KB_FW2F);
        const uint4* s2p = (const uint4*)g_fw2f;
        for (int i = tid; i < 1024; i += 256) d2[i] = s2p[i];
        if (tid < 128) {
            float be = beta[tid], ga = gamma[tid];
            ((float2*)(sm + KB_E2  ))[tid] = make_float2(be * (1.0f / (W2SCL * SSCL)), be * b2[tid]);
            ((float2*)(sm + KB_ELN ))[tid] = make_float2(ln2s[tid], ln2b[tid]);
            ((float2*)(sm + KB_EGAM))[tid] = make_float2(ga, ga * bf2[tid]);
            ((float*)(sm + KB_ATT))[tid] = g_att[batch * 128 + tid];
        }
        if (tid < 256) {
            int n = tid, o = (n >> 1) + (n & 1) * 128;
            ((float*)(sm + KB_EBF1))[n] = bf1[o];
        }
    }
    __syncthreads();

    // ---- fold att into staged fp8 w2 frags (k-indexed) ----
    {
        const float* attv = (const float*)(sm + KB_ATT);
        uint32_t* p = (uint32_t*)(sm + KB_FW2F);
        for (int i = tid; i < 4096; i += 256) {
            int e = i & 1, lane2 = (i >> 2) & 31, ks = i >> 10;
            int k0 = 32 * ks + 4 * (lane2 & 3) + 16 * e;
            uint32_t v = p[i], nv = 0;
            #pragma unroll
            for (int j = 0; j < 4; ++j) {
                float f = e4m3f((uint8_t)(v >> (8 * j))) * attv[k0 + j];
                nv |= (uint32_t)f2e4m3(f) << (8 * j);
            }
            p[i] = nv;
        }
    }
    __syncthreads();

    const float2* e2p  = (const float2*)(sm + KB_E2);
    const float2* elnp = (const float2*)(sm + KB_ELN);
    const float*  ebfp = (const float*)(sm + KB_EBF1);
    const float2* egap = (const float2*)(sm + KB_EGAM);
    float* xms = (float*)(sm + KB_XM);

    auto prefetch_s = [&](int t) {
        #pragma unroll
        for (int i = 0; i < 4; ++i) {
            int u = lane + 32 * i, row = u >> 3, ch = u & 7;
            uint32_t dst = sm_base + KB_S8 + (uint32_t)(m0 + row) * SA8 + ch * 16;
            CP_ASYNC16(dst, g_s8 + ((size_t)(t * 128 + m0 + row)) * 128 + ch * 16);
        }
    };
    auto prefetch_x = [&](int t) {
        const float* xg = x + ((size_t)(t * 128 + m0)) * 128;
        #pragma unroll
        for (int i = 0; i < 16; ++i) {
            int gidx = i * 32 + lane;
            int row = gidx >> 5, c16 = gidx & 31;
            uint32_t dst = sm_base + KB_XM + (uint32_t)(m0 + row) * 528 + c16 * 16;
            CP_ASYNC16(dst, xg + (size_t)row * 128 + c16 * 4);
        }
    };

    prefetch_s(tbase); CP_COMMIT();
    prefetch_x(tbase); CP_COMMIT();

    #pragma unroll 1
    for (int it = 0; it < 16; ++it) {
        const int tile = tbase + 18 * it;
        const char* ar0 = sm + (m0 + r) * SA;
        const char* a8r = sm + KB_S8 + (m0 + r) * SA8;

        CP_WAIT1();
        __syncwarp();

        // ---- GEMM w2 fp8 (A = s*SSCL, B = w2*att*W2SCL) ----
        float acc[16][4];
        #pragma unroll
        for (int nb = 0; nb < 16; ++nb)
            { acc[nb][0]=0.f; acc[nb][1]=0.f; acc[nb][2]=0.f; acc[nb][3]=0.f; }
        #pragma unroll 2
        for (int ks = 0; ks < 4; ++ks) {
            int kb = 32 * ks + 4 * q;
            uint32_t a0 = *(const uint32_t*)(a8r + kb);
            uint32_t a1 = *(const uint32_t*)(a8r + 8 * SA8 + kb);
            uint32_t a2 = *(const uint32_t*)(a8r + kb + 16);
            uint32_t a3 = *(const uint32_t*)(a8r + 8 * SA8 + kb + 16);
            const uint4* fb = (const uint4*)(sm + KB_FW2F) + ks * 256 + lane;
            #pragma unroll
            for (int nbp = 0; nbp < 8; ++nbp) {
                uint4 b = fb[nbp * 32];
                mma_fp8(acc[2*nbp],   a0, a1, a2, a3, b.x, b.y);
                mma_fp8(acc[2*nbp+1], a0, a1, a2, a3, b.z, b.w);
            }
        }

        // ---- xm = x + beta*(d+b2); stash f32; LN2 stats via quad shfl ----
        CP_WAIT0();
        __syncwarp();
        float s1a = 0.f, s2a = 0.f, s1b = 0.f, s2b = 0.f;
        #pragma unroll
        for (int nb = 0; nb < 16; ++nb) {
            int n0 = 8 * nb + 2 * q;
            float2 e0 = e2p[n0], e1 = e2p[n0 + 1];
            float* pa = xms + (m0 + r)     * 132 + n0;
            float* pb = xms + (m0 + r + 8) * 132 + n0;
            float2 xa = *(float2*)pa;
            float2 xb = *(float2*)pb;
            float m00 = xa.x + acc[nb][0]*e0.x + e0.y;
            float m01 = xa.y + acc[nb][1]*e1.x + e1.y;
            float m10 = xb.x + acc[nb][2]*e0.x + e0.y;
            float m11 = xb.y + acc[nb][3]*e1.x + e1.y;
            *(float2*)pa = make_float2(m00, m01);
            *(float2*)pb = make_float2(m10, m11);
            s1a += m00 + m01; s2a += m00*m00 + m01*m01;
            s1b += m10 + m11; s2b += m10*m10 + m11*m11;
        }
        s1a += __shfl_xor_sync(0xffffffffu, s1a, 1); s1a += __shfl_xor_sync(0xffffffffu, s1a, 2);
        s2a += __shfl_xor_sync(0xffffffffu, s2a, 1); s2a += __shfl_xor_sync(0xffffffffu, s2a, 2);
        s1b += __shfl_xor_sync(0xffffffffu, s1b, 1); s1b += __shfl_xor_sync(0xffffffffu, s1b, 2);
        s2b += __shfl_xor_sync(0xffffffffu, s2b, 1); s2b += __shfl_xor_sync(0xffffffffu, s2b, 2);
        const float mua = s1a * (1.f/128.f);
        const float rsa = rsqrtf(fmaxf(s2a * (1.f/128.f) - mua*mua, 0.f) + EPS);
        const float mub = s1b * (1.f/128.f);
        const float rsb = rsqrtf(fmaxf(s2b * (1.f/128.f) - mub*mub, 0.f) + EPS);

        // ---- A2 = LN2(xm) -> atile bf16 ----
        #pragma unroll
        for (int nb = 0; nb < 16; ++nb) {
            int n0 = 8 * nb + 2 * q;
            float2 p0 = elnp[n0], p1 = elnp[n0 + 1];
            float2 va = *(const float2*)(xms + (m0 + r)     * 132 + n0);
            float2 vb = *(const float2*)(xms + (m0 + r + 8) * 132 + n0);
            *(uint32_t*)(sm + (m0 + r)     * SA + n0 * 2) =
                pack_bf2((va.x-mua)*rsa*p0.x+p0.y, (va.y-mua)*rsa*p1.x+p1.y);
            *(uint32_t*)(sm + (m0 + r + 8) * SA + n0 * 2) =
                pack_bf2((vb.x-mub)*rsb*p0.x+p0.y, (vb.y-mub)*rsb*p1.x+p1.y);
        }
        __syncwarp();

        // ---- GEMM wf1 (paired, 2 x n128 passes) ----
        uint32_t gsave[16];
        #pragma unroll 1
        for (int half = 0; half < 2; ++half) {
            float acc2[16][4];
            #pragma unroll
            for (int nb = 0; nb < 16; ++nb)
                { acc2[nb][0]=0.f; acc2[nb][1]=0.f; acc2[nb][2]=0.f; acc2[nb][3]=0.f; }
            #pragma unroll 2
            for (int ks = 0; ks < 8; ++ks) {
                int kb = 32 * ks + 4 * q;
                uint32_t a0 = *(const uint32_t*)(ar0 + kb);
                uint32_t a1 = *(const uint32_t*)(ar0 + 8 * SA + kb);
                uint32_t a2 = *(const uint32_t*)(ar0 + kb + 16);
                uint32_t a3 = *(const uint32_t*)(ar0 + 8 * SA + kb + 16);
                const uint4* fb = (const uint4*)(sm + KB_FWF1) + (ks * 2 + half) * 256 + lane;
                #pragma unroll
                for (int nbp = 0; nbp < 8; ++nbp) {
                    uint4 b = fb[nbp * 32];
                    mma_bf16(acc2[2*nbp],   a0, a1, a2, a3, b.x, b.y);
                    mma_bf16(acc2[2*nbp+1], a0, a1, a2, a3, b.z, b.w);
                }
            }
            #pragma unroll
            for (int nb = 0; nb < 16; ++nb) {
                int nbg = half * 16 + nb;
                int n0 = 8 * nbg + 2 * q, j = 4 * nbg + q;
                float e0 = ebfp[n0], e1 = ebfp[n0 + 1];
                float lo = (acc2[nb][0] + e0) * (acc2[nb][1] + e1);
                float hi = (acc2[nb][2] + e0) * (acc2[nb][3] + e1);
                if (half == 0) {
                    gsave[nb] = pack_bf2(lo, hi);
                } else {
                    *(__nv_bfloat16*)(sm + (m0 + r)     * SA + j * 2) = __float2bfloat16(lo);
                    *(__nv_bfloat16*)(sm + (m0 + r + 8) * SA + j * 2) = __float2bfloat16(hi);
                }
            }
            __syncwarp();
        }
        #pragma unroll
        for (int nb = 0; nb < 16; ++nb) {
            int j = 4 * nb + q;
            float2 v = unpack_bf2(gsave[nb]);
            *(__nv_bfloat16*)(sm + (m0 + r)     * SA + j * 2) = __float2bfloat16(v.x);
            *(__nv_bfloat16*)(sm + (m0 + r + 8) * SA + j * 2) = __float2bfloat16(v.y);
        }
        __syncwarp();

        // ---- GEMM wf2 (n128), frags via LDG.128 ----
        float acc3[16][4];
        #pragma unroll
        for (int nb = 0; nb < 16; ++nb)
            { acc3[nb][0]=0.f; acc3[nb][1]=0.f; acc3[nb][2]=0.f; acc3[nb][3]=0.f; }
        #pragma unroll 2
        for (int ks = 0; ks < 8; ++ks) {
            int kb = 32 * ks + 4 * q;
            uint32_t a0 = *(const uint32_t*)(ar0 + kb);
            uint32_t a1 = *(const uint32_t*)(ar0 + 8 * SA + kb);
            uint32_t a2 = *(const uint32_t*)(ar0 + kb + 16);
            uint32_t a3 = *(const uint32_t*)(ar0 + 8 * SA + kb + 16);
            const uint4* fb = (const uint4*)g_fwf2 + ks * 256 + lane;
            #pragma unroll
            for (int nbp = 0; nbp < 8; ++nbp) {
                uint4 b = __ldg(fb + nbp * 32);
                mma_bf16(acc3[2*nbp],   a0, a1, a2, a3, b.x, b.y);
                mma_bf16(acc3[2*nbp+1], a0, a1, a2, a3, b.z, b.w);
            }
        }

        // ---- prefetch next tile's s (s8 region dead after w2 GEMM) ----
        if (it < 15) { prefetch_s(tile + 18); CP_COMMIT(); }

        // ---- out = xm + gamma*(d+bf2) ----
        float* or0 = out + ((size_t)(tile * 128 + m0 + r)) * 128;
        float* or8 = or0 + (size_t)8 * 128;
        #pragma unroll
        for (int nb = 0; nb < 16; ++nb) {
            int n0 = 8 * nb + 2 * q;
            float2 g0 = egap[n0], g1 = egap[n0 + 1];
            float2 va = *(const float2*)(xms + (m0 + r)     * 132 + n0);
            float2 vb = *(const float2*)(xms + (m0 + r + 8) * 132 + n0);
            *(float2*)(or0 + n0) = make_float2(va.x + acc3[nb][0]*g0.x + g0.y,
                                               va.y + acc3[nb][1]*g1.x + g1.y);
            *(float2*)(or8 + n0) = make_float2(vb.x + acc3[nb][2]*g0.x + g0.y,
                                               vb.y + acc3[nb][3]*g1.x + g1.y);
        }

        // ---- prefetch next tile's x (xm region dead now) ----
        if (it < 15) { prefetch_x(tile + 18); CP_COMMIT(); }
        __syncwarp();
    }
}

// =====================================================================
// launch
// =====================================================================
extern "C" void kernel_launch(void* const* d_in, const int* in_sizes, int n_in,
                              void* d_out, int out_size)
{
    (void)in_sizes; (void)n_in; (void)out_size;
    const float* x     = (const float*)d_in[0];
    const float* ln1s  = (const float*)d_in[1];
    const float* ln1b  = (const float*)d_in[2];
    const float* w1    = (const float*)d_in[3];
    const float* b1    = (const float*)d_in[4];
    const float* wdw   = (const float*)d_in[5];
    const float* bdw   = (const float*)d_in[6];
    const float* wse   = (const float*)d_in[7];
    const float* bse   = (const float*)d_in[8];
    const float* w2    = (const float*)d_in[9];
    const float* b2    = (const float*)d_in[10];
    const float* ln2s  = (const float*)d_in[11];
    const float* ln2b  = (const float*)d_in[12];
    const float* wf1   = (const float*)d_in[13];
    const float* bf1   = (const float*)d_in[14];
    const float* wf2   = (const float*)d_in[15];
    const float* bf2   = (const float*)d_in[16];
    const float* beta  = (const float*)d_in[17];
    const float* gamma = (const float*)d_in[18];
    float* out = (float*)d_out;

    cudaFuncSetAttribute(kA_spatial, cudaFuncAttributeMaxDynamicSharedMemorySize, KA_SMEM);
    cudaFuncSetAttribute(kB_ffn,     cudaFuncAttributeMaxDynamicSharedMemorySize, KB_SMEM);

    k0_frags<<<64, 256>>>(w1, w2, wf1, wf2);
    kA_spatial<<<GRID_A, 256, KA_SMEM>>>(x, ln1s, ln1b, b1, wdw, bdw);
    k2_se<<<B_, 512>>>(wse, bse);
    kB_ffn<<<GRID_B, 256, KB_SMEM>>>(x, b2, beta, ln2s, ln2b, bf1, bf2, gamma, out);
}

// round 15
// speedup vs baseline: 1.2618x; 1.0075x over previous
#include <cuda_runtime.h>
#include <cuda_bf16.h>
#include <cuda_fp8.h>
#include <cstdint>

#define B_     8
#define C_     128
#define PIXPB  36864
#define NPIX   294912
#define NT     2304             // 128-pixel tiles
#define TPB    288              // tiles per batch
#define EPS    1e-6f
#define GRID_A 296
#define GRID_B 144              // 18 CTAs per batch x 16 tiles
#define SA     304              // bf16 A-tile row stride bytes (conflict-free)
#define SA8    144              // fp8 A-tile row stride bytes (conflict-free)
#define W1SCL  8.0f             // w1 pre-scale into e4m3 normal range
#define W2SCL  64.0f            // w2 pre-scale
#define SSCL   256.0f           // s pre-scale for e4m3 storage
#define WF1SCL 8.0f             // wf1 pre-scale
#define IVF1   (1.0f / WF1SCL)

// ---------------- device globals (no allocation) ----------------
__device__ uint8_t  g_s8[(size_t)NPIX * 128]; // gated branch, e4m3 x SSCL, [pix][128]
__device__ float    g_gpart[NT * 128];        // per-tile GAP partials
__device__ float    g_att[B_ * C_];
// fp8 frag images (m16n8k32): [ks4][(half)][nbp8][lane][e4] u32 (4x e4m3)
__device__ uint32_t g_fw1 [4 * 2 * 8 * 32 * 4];  // w1 (pair-permuted, x8), N=256
__device__ uint32_t g_fwf1[4 * 2 * 8 * 32 * 4];  // wf1 (pair-permuted, x8), N=256
__device__ uint32_t g_fw2f[4 * 8 * 32 * 4];      // w2 (x64), N=128
// bf16 pair-packed image: [ks8][nbp][lane][e4] u32 (bf16x2)
__device__ uint32_t g_fwf2[8 * 8 * 32 * 4];      // wf2, N=128

__device__ __forceinline__ uint32_t pack_bf2(float a, float b) {
    __nv_bfloat162 h = __floats2bfloat162_rn(a, b);   // low = a
    return *reinterpret_cast<uint32_t*>(&h);
}
__device__ __forceinline__ float2 unpack_bf2(uint32_t w) {
    __nv_bfloat162 h = *reinterpret_cast<const __nv_bfloat162*>(&w);
    return make_float2(__low2float(h), __high2float(h));
}
__device__ __forceinline__ uint16_t pack_e4m3x2(float a, float b) {
    uint16_t v;
    asm("cvt.rn.satfinite.e4m3x2.f32 %0, %1, %2;" : "=h"(v) : "f"(b), "f"(a)); // low = a
    return v;
}
__device__ __forceinline__ uint32_t pack_e4m3x4(float f0, float f1, float f2, float f3) {
    uint16_t lo = pack_e4m3x2(f0, f1), hi = pack_e4m3x2(f2, f3);
    uint32_t r; asm("mov.b32 %0, {%1, %2};" : "=r"(r) : "h"(lo), "h"(hi));
    return r;
}
__device__ __forceinline__ uint8_t f2e4m3(float f) {
    __nv_fp8_e4m3 v(f);
    return *reinterpret_cast<uint8_t*>(&v);
}
__device__ __forceinline__ float e4m3f(uint8_t b) {
    __nv_fp8_e4m3 v = *reinterpret_cast<__nv_fp8_e4m3*>(&b);
    return float(v);
}
__device__ __forceinline__ void mma_bf16(float* c, uint32_t a0, uint32_t a1,
                                         uint32_t a2, uint32_t a3,
                                         uint32_t b0, uint32_t b1) {
    asm volatile(
        "mma.sync.aligned.m16n8k16.row.col.f32.bf16.bf16.f32 "
        "{%0,%1,%2,%3}, {%4,%5,%6,%7}, {%8,%9}, {%0,%1,%2,%3};\n"
        : "+f"(c[0]), "+f"(c[1]), "+f"(c[2]), "+f"(c[3])
        : "r"(a0), "r"(a1), "r"(a2), "r"(a3), "r"(b0), "r"(b1));
}
__device__ __forceinline__ void mma_fp8(float* c, uint32_t a0, uint32_t a1,
                                        uint32_t a2, uint32_t a3,
                                        uint32_t b0, uint32_t b1) {
    asm volatile(
        "mma.sync.aligned.m16n8k32.row.col.f32.e4m3.e4m3.f32 "
        "{%0,%1,%2,%3}, {%4,%5,%6,%7}, {%8,%9}, {%0,%1,%2,%3};\n"
        : "+f"(c[0]), "+f"(c[1]), "+f"(c[2]), "+f"(c[3])
        : "r"(a0), "r"(a1), "r"(a2), "r"(a3), "r"(b0), "r"(b1));
}
__device__ __forceinline__ uint32_t smem_u32(const void* p) {
    uint32_t a;
    asm("{ .reg .u64 t; cvta.to.shared.u64 t, %1; cvt.u32.u64 %0, t; }" : "=r"(a) : "l"(p));
    return a;
}
#define CP_ASYNC16(dst, src) \
    asm volatile("cp.async.ca.shared.global [%0], [%1], 16;" :: "r"(dst), "l"(src))
#define CP_COMMIT()  asm volatile("cp.async.commit_group;" ::: "memory")
#define CP_WAIT1()   asm volatile("cp.async.wait_group 1;" ::: "memory")
#define CP_WAIT0()   asm volatile("cp.async.wait_group 0;" ::: "memory")

// =====================================================================
// k0: fragment images.
// fp8 m16n8k32 col-B frag: lane holds B[k..k+3][n], n = 8nb + lane/4,
//   k = 32ks + 4*(lane%4) + 16e.  bf16 m16n8k16: k = 16ks + 2*(lane%4) + 8e.
// w1/wf1 pair-permuted: img col n -> orig col (n>>1)+(n&1)*128
// =====================================================================
__global__ void k0_frags(const float* __restrict__ w1, const float* __restrict__ w2,
                         const float* __restrict__ wf1, const float* __restrict__ wf2)
{
    int i0 = blockIdx.x * blockDim.x + threadIdx.x, str = gridDim.x * blockDim.x;
    // w1 + wf1 fp8 images: 8192 words each
    for (int i = i0; i < 8192; i += str) {
        int e4 = i & 3, lane = (i >> 2) & 31, nbp = (i >> 7) & 7;
        int half = (i >> 10) & 1, ks = i >> 11;
        int nbg = half * 16 + 2 * nbp + (e4 >> 1);
        int e = e4 & 1;
        int n = 8 * nbg + (lane >> 2);
        int k = 32 * ks + 4 * (lane & 3) + 16 * e;
        int o = (n >> 1) + (n & 1) * 128;
        uint32_t wa = 0, wb = 0;
        #pragma unroll
        for (int j = 0; j < 4; ++j) {
            wa |= (uint32_t)f2e4m3(w1 [(k + j) * 256 + o] * W1SCL)  << (8 * j);
            wb |= (uint32_t)f2e4m3(wf1[(k + j) * 256 + o] * WF1SCL) << (8 * j);
        }
        g_fw1 [i] = wa;
        g_fwf1[i] = wb;
    }
    // w2 fp8 image: 4096 words
    for (int i = i0; i < 4096; i += str) {
        int e4 = i & 3, lane = (i >> 2) & 31, nbp = (i >> 7) & 7, ks = i >> 10;
        int nb = 2 * nbp + (e4 >> 1);
        int e = e4 & 1;
        int n = 8 * nb + (lane >> 2);
        int k = 32 * ks + 4 * (lane & 3) + 16 * e;
        uint32_t w = 0;
        #pragma unroll
        for (int j = 0; j < 4; ++j)
            w |= (uint32_t)f2e4m3(w2[(k + j) * 128 + n] * W2SCL) << (8 * j);
        g_fw2f[i] = w;
    }
    // wf2 bf16 image: 8192 words
    for (int i = i0; i < 8192; i += str) {
        int e4 = i & 3, lane = (i >> 2) & 31, nbp = (i >> 7) & 7, ks = i >> 10;
        int nb = 2 * nbp + (e4 >> 1);
        int e = e4 & 1;
        int n = 8 * nb + (lane >> 2);
        int k = 16 * ks + 2 * (lane & 3) + 8 * e;
        g_fwf2[i] = pack_bf2(wf2[k * 128 + n], wf2[(k + 1) * 128 + n]);
    }
}

// =====================================================================
// kA: 256 thr, 8 warps x 16 rows, 2 CTAs/SM.  (unchanged from R14)
// =====================================================================
#define KA_FW1  18432
#define KA_EW   (KA_FW1 + 32768)
#define KA_LN   (KA_EW + 2048)
#define KA_GAP  (KA_LN + 1024)
#define KA_SMEM (KA_GAP + 4096)

__global__ void __launch_bounds__(256, 2)
kA_spatial(const float* __restrict__ x,
           const float* __restrict__ ln1s, const float* __restrict__ ln1b,
           const float* __restrict__ b1,   const float* __restrict__ wdw,
           const float* __restrict__ bdw)
{
    extern __shared__ char sm[];
    const int tid = threadIdx.x, lane = tid & 31, warp = tid >> 5;
    const int q = lane & 3, r = lane >> 2, m0 = warp * 16;

    {
        uint4* dst = (uint4*)(sm + KA_FW1);
        const uint4* src = (const uint4*)g_fw1;
        for (int i = tid; i < 2048; i += 256) dst[i] = src[i];
        if (tid < 256) {
            int n = tid, o = (n >> 1) + (n & 1) * 128;
            float w = wdw[o];
            ((float2*)(sm + KA_EW))[n] = make_float2(w * (1.0f / W1SCL), b1[o] * w + bdw[o]);
        }
        if (tid < 128)
            ((float2*)(sm + KA_LN))[tid] = make_float2(ln1s[tid], ln1b[tid]);
    }
    __syncthreads();

    const float2* ewp = (const float2*)(sm + KA_EW);
    const float2* lnp = (const float2*)(sm + KA_LN);
    float* gapw = (float*)(sm + KA_GAP);
    const int pl = tid >> 1, h = tid & 1;

    for (int tile = blockIdx.x; tile < NT; tile += GRID_A) {
        const float4* xr = (const float4*)x + ((size_t)(tile * 128 + pl)) * 32 + h * 16;
        float4 xv[16];
        float s1 = 0.f, s2 = 0.f;
        #pragma unroll
        for (int i = 0; i < 16; ++i) {
            xv[i] = xr[i];
            s1 += xv[i].x + xv[i].y + xv[i].z + xv[i].w;
            s2 += xv[i].x*xv[i].x + xv[i].y*xv[i].y + xv[i].z*xv[i].z + xv[i].w*xv[i].w;
        }
        s1 += __shfl_xor_sync(0xffffffffu, s1, 1);
        s2 += __shfl_xor_sync(0xffffffffu, s2, 1);
        const float mu = s1 * (1.f/128.f);
        const float rs = rsqrtf(fmaxf(s2 * (1.f/128.f) - mu*mu, 0.f) + EPS);

        char* row8 = sm + pl * SA8 + h * 64;
        #pragma unroll
        for (int j = 0; j < 8; ++j) {
            float4 v0 = xv[2*j], v1 = xv[2*j+1];
            int c = h * 64 + 8 * j;
            float2 p0 = lnp[c],   p1 = lnp[c+1], p2 = lnp[c+2], p3 = lnp[c+3];
            float2 p4 = lnp[c+4], p5 = lnp[c+5], p6 = lnp[c+6], p7 = lnp[c+7];
            uint32_t w0 = pack_e4m3x4((v0.x-mu)*rs*p0.x+p0.y, (v0.y-mu)*rs*p1.x+p1.y,
                                      (v0.z-mu)*rs*p2.x+p2.y, (v0.w-mu)*rs*p3.x+p3.y);
            uint32_t w1w = pack_e4m3x4((v1.x-mu)*rs*p4.x+p4.y, (v1.y-mu)*rs*p5.x+p5.y,
                                       (v1.z-mu)*rs*p6.x+p6.y, (v1.w-mu)*rs*p7.x+p7.y);
            *(uint2*)(row8 + j * 8) = make_uint2(w0, w1w);
        }
        __syncwarp();

        const char* a8r = sm + (m0 + r) * SA8;
        uint32_t gsave[16];

        #pragma unroll 1
        for (int half = 0; half < 2; ++half) {
            float acc[16][4];
            #pragma unroll
            for (int nb = 0; nb < 16; ++nb)
                { acc[nb][0]=0.f; acc[nb][1]=0.f; acc[nb][2]=0.f; acc[nb][3]=0.f; }

            #pragma unroll 2
            for (int ks = 0; ks < 4; ++ks) {
                int kb = 32 * ks + 4 * q;
                uint32_t a0 = *(const uint32_t*)(a8r + kb);
                uint32_t a1 = *(const uint32_t*)(a8r + 8 * SA8 + kb);
                uint32_t a2 = *(const uint32_t*)(a8r + kb + 16);
                uint32_t a3 = *(const uint32_t*)(a8r + 8 * SA8 + kb + 16);
                const uint4* fb = (const uint4*)(sm + KA_FW1) + (ks * 2 + half) * 256 + lane;
                #pragma unroll
                for (int nbp = 0; nbp < 8; ++nbp) {
                    uint4 b = fb[nbp * 32];
                    mma_fp8(acc[2*nbp],   a0, a1, a2, a3, b.x, b.y);
                    mma_fp8(acc[2*nbp+1], a0, a1, a2, a3, b.z, b.w);
                }
            }

            #pragma unroll
            for (int nb = 0; nb < 16; ++nb) {
                int nbg = half * 16 + nb;
                int n0 = 8 * nbg + 2 * q, j = 4 * nbg + q;
                float2 e0 = ewp[n0], e1 = ewp[n0 + 1];
                float lo = (acc[nb][0]*e0.x + e0.y) * (acc[nb][1]*e1.x + e1.y);
                float hi = (acc[nb][2]*e0.x + e0.y) * (acc[nb][3]*e1.x + e1.y);
                float g = lo + hi;
                g += __shfl_xor_sync(0xffffffffu, g, 4);
                g += __shfl_xor_sync(0xffffffffu, g, 8);
                g += __shfl_xor_sync(0xffffffffu, g, 16);
                if (r == 0) gapw[warp * 128 + j] = g;
                if (half == 0) {
                    gsave[nb] = pack_bf2(lo, hi);
                } else {
                    *(uint8_t*)(sm + (m0 + r)     * SA8 + j) = f2e4m3(lo * SSCL);
                    *(uint8_t*)(sm + (m0 + r + 8) * SA8 + j) = f2e4m3(hi * SSCL);
                }
            }
            __syncwarp();
        }
        #pragma unroll
        for (int nb = 0; nb < 16; ++nb) {
            int j = 4 * nb + q;
            float2 v = unpack_bf2(gsave[nb]);
            *(uint8_t*)(sm + (m0 + r)     * SA8 + j) = f2e4m3(v.x * SSCL);
            *(uint8_t*)(sm + (m0 + r + 8) * SA8 + j) = f2e4m3(v.y * SSCL);
        }
        __syncwarp();

        #pragma unroll
        for (int i = 0; i < 4; ++i) {
            int u = lane + 32 * i, row = u >> 3, ch = u & 7;
            uint4 v = *(const uint4*)(sm + (m0 + row) * SA8 + ch * 16);
            ((uint4*)g_s8)[((size_t)(tile * 128 + m0 + row)) * 8 + ch] = v;
        }

        __syncthreads();
        if (tid < 128) {
            float s = 0.f;
            #pragma unroll
            for (int w = 0; w < 8; ++w) s += gapw[w * 128 + tid];
            g_gpart[tile * 128 + tid] = s;
        }
        __syncthreads();
    }
}

// =====================================================================
// k2_se (unchanged)
// =====================================================================
__global__ void k2_se(const float* __restrict__ wse, const float* __restrict__ bse)
{
    __shared__ float red[4][128];
    __shared__ float gap[128];
    __shared__ float ps[4][128];
    const int b = blockIdx.x, tid = threadIdx.x;
    const int c = tid & 127, g = tid >> 7;

    float s = 0.f;
    const float* src = g_gpart + (size_t)(b * TPB + g * 72) * 128 + c;
    #pragma unroll 8
    for (int i = 0; i < 72; ++i) s += src[(size_t)i * 128];
    red[g][c] = s;
    __syncthreads();
    if (tid < 128)
        gap[tid] = ((red[0][tid] + red[1][tid]) + (red[2][tid] + red[3][tid])) * (1.f / PIXPB);
    __syncthreads();

    float a = 0.f;
    #pragma unroll 8
    for (int kk = 0; kk < 32; ++kk) {
        int k = 32 * g + kk;
        a += gap[k] * wse[k * 128 + c];
    }
    ps[g][c] = a;
    __syncthreads();
    if (tid < 128)
        g_att[b * 128 + tid] = bse[tid] +
            ((ps[0][tid] + ps[1][tid]) + (ps[2][tid] + ps[3][tid]));
}

// =====================================================================
// kB: fp8 w2 + fp8 wf1 (LN2 out -> dead s8 region). wf2 stays bf16.
//     256 thr, 8 warps x 16 rows, batch-fixed CTAs, cp.async prefetch.
// =====================================================================
#define KB_XM    38912                      // atile bf16 (gate) at 0..38912
#define KB_FWF1  (KB_XM + 67584)            // fp8 wf1 image, 32768
#define KB_FW2F  (KB_FWF1 + 32768)          // fp8 w2 image, 16384
#define KB_S8    (KB_FW2F + 16384)          // s fp8 / LN2 fp8 tile, 18432
#define KB_E2    (KB_S8 + 18432)
#define KB_ELN   (KB_E2 + 1024)
#define KB_EBF1  (KB_ELN + 1024)
#define KB_EGAM  (KB_EBF1 + 1024)
#define KB_ATT   (KB_EGAM + 1024)
#define KB_SMEM  (KB_ATT + 512)             // 178688

__global__ void __launch_bounds__(256, 1)
kB_ffn(const float* __restrict__ x,
       const float* __restrict__ b2,   const float* __restrict__ beta,
       const float* __restrict__ ln2s, const float* __restrict__ ln2b,
       const float* __restrict__ bf1,  const float* __restrict__ bf2,
       const float* __restrict__ gamma, float* __restrict__ out)
{
    extern __shared__ char sm[];
    const int tid = threadIdx.x, lane = tid & 31, warp = tid >> 5;
    const int q = lane & 3, r = lane >> 2, m0 = warp * 16;
    const uint32_t sm_base = smem_u32(sm);
    const int batch = blockIdx.x / 18, sub = blockIdx.x % 18;
    const int tbase = batch * TPB + sub;

    {
        uint4* d1 = (uint4*)(sm + KB_FWF1);
        const uint4* s1p = (const uint4*)g_fwf1;
        for (int i = tid; i < 2048; i += 256) d1[i] = s1p[i];
        uint4* d2 = (uint4*)(sm + KB_FW2F);
        const uint4* s2p = (const uint4*)g_fw2f;
        for (int i = tid; i < 1024; i += 256) d2[i] = s2p[i];
        if (tid < 128) {
            float be = beta[tid], ga = gamma[tid];
            ((float2*)(sm + KB_E2  ))[tid] = make_float2(be * (1.0f / (W2SCL * SSCL)), be * b2[tid]);
            ((float2*)(sm + KB_ELN ))[tid] = make_float2(ln2s[tid], ln2b[tid]);
            ((float2*)(sm + KB_EGAM))[tid] = make_float2(ga, ga * bf2[tid]);
            ((float*)(sm + KB_ATT))[tid] = g_att[batch * 128 + tid];
        }
        if (tid < 256) {
            int n = tid, o = (n >> 1) + (n & 1) * 128;
            ((float*)(sm + KB_EBF1))[n] = bf1[o];
        }
    }
    __syncthreads();

    // fold att into staged fp8 w2 frags (k-indexed)
    {
        const float* attv = (const float*)(sm + KB_ATT);
        uint32_t* p = (uint32_t*)(sm + KB_FW2F);
        for (int i = tid; i < 4096; i += 256) {
            int e = i & 1, lane2 = (i >> 2) & 31, ks = i >> 10;
            int k0 = 32 * ks + 4 * (lane2 & 3) + 16 * e;
            uint32_t v = p[i], nv = 0;
            #pragma unroll
            for (int j = 0; j < 4; ++j) {
                float f = e4m3f((uint8_t)(v >> (8 * j))) * attv[k0 + j];
                nv |= (uint32_t)f2e4m3(f) << (8 * j);
            }
            p[i] = nv;
        }
    }
    __syncthreads();

    const float2* e2p  = (const float2*)(sm + KB_E2);
    const float2* elnp = (const float2*)(sm + KB_ELN);
    const float*  ebfp = (const float*)(sm + KB_EBF1);
    const float2* egap = (const float2*)(sm + KB_EGAM);
    float* xms = (float*)(sm + KB_XM);

    auto prefetch_s = [&](int t) {
        #pragma unroll
        for (int i = 0; i < 4; ++i) {
            int u = lane + 32 * i, row = u >> 3, ch = u & 7;
            uint32_t dst = sm_base + KB_S8 + (uint32_t)(m0 + row) * SA8 + ch * 16;
            CP_ASYNC16(dst, g_s8 + ((size_t)(t * 128 + m0 + row)) * 128 + ch * 16);
        }
    };
    auto prefetch_x = [&](int t) {
        const float* xg = x + ((size_t)(t * 128 + m0)) * 128;
        #pragma unroll
        for (int i = 0; i < 16; ++i) {
            int gidx = i * 32 + lane;
            int row = gidx >> 5, c16 = gidx & 31;
            uint32_t dst = sm_base + KB_XM + (uint32_t)(m0 + row) * 528 + c16 * 16;
            CP_ASYNC16(dst, xg + (size_t)row * 128 + c16 * 4);
        }
    };

    prefetch_s(tbase); CP_COMMIT();
    prefetch_x(tbase); CP_COMMIT();

    #pragma unroll 1
    for (int it = 0; it < 16; ++it) {
        const int tile = tbase + 18 * it;
        const char* ar0 = sm + (m0 + r) * SA;
        const char* a8r = sm + KB_S8 + (m0 + r) * SA8;

        CP_WAIT1();
        __syncwarp();

        // ---- GEMM w2 fp8 ----
        float acc[16][4];
        #pragma unroll
        for (int nb = 0; nb < 16; ++nb)
            { acc[nb][0]=0.f; acc[nb][1]=0.f; acc[nb][2]=0.f; acc[nb][3]=0.f; }
        #pragma unroll 2
        for (int ks = 0; ks < 4; ++ks) {
            int kb = 32 * ks + 4 * q;
            uint32_t a0 = *(const uint32_t*)(a8r + kb);
            uint32_t a1 = *(const uint32_t*)(a8r + 8 * SA8 + kb);
            uint32_t a2 = *(const uint32_t*)(a8r + kb + 16);
            uint32_t a3 = *(const uint32_t*)(a8r + 8 * SA8 + kb + 16);
            const uint4* fb = (const uint4*)(sm + KB_FW2F) + ks * 256 + lane;
            #pragma unroll
            for (int nbp = 0; nbp < 8; ++nbp) {
                uint4 b = fb[nbp * 32];
                mma_fp8(acc[2*nbp],   a0, a1, a2, a3, b.x, b.y);
                mma_fp8(acc[2*nbp+1], a0, a1, a2, a3, b.z, b.w);
            }
        }

        // ---- xm = x + beta*(d+b2); stash f32; LN2 stats via quad shfl ----
        CP_WAIT0();
        __syncwarp();
        float s1a = 0.f, s2a = 0.f, s1b = 0.f, s2b = 0.f;
        #pragma unroll
        for (int nb = 0; nb < 16; ++nb) {
            int n0 = 8 * nb + 2 * q;
            float2 e0 = e2p[n0], e1 = e2p[n0 + 1];
            float* pa = xms + (m0 + r)     * 132 + n0;
            float* pb = xms + (m0 + r + 8) * 132 + n0;
            float2 xa = *(float2*)pa;
            float2 xb = *(float2*)pb;
            float m00 = xa.x + acc[nb][0]*e0.x + e0.y;
            float m01 = xa.y + acc[nb][1]*e1.x + e1.y;
            float m10 = xb.x + acc[nb][2]*e0.x + e0.y;
            float m11 = xb.y + acc[nb][3]*e1.x + e1.y;
            *(float2*)pa = make_float2(m00, m01);
            *(float2*)pb = make_float2(m10, m11);
            s1a += m00 + m01; s2a += m00*m00 + m01*m01;
            s1b += m10 + m11; s2b += m10*m10 + m11*m11;
        }
        s1a += __shfl_xor_sync(0xffffffffu, s1a, 1); s1a += __shfl_xor_sync(0xffffffffu, s1a, 2);
        s2a += __shfl_xor_sync(0xffffffffu, s2a, 1); s2a += __shfl_xor_sync(0xffffffffu, s2a, 2);
        s1b += __shfl_xor_sync(0xffffffffu, s1b, 1); s1b += __shfl_xor_sync(0xffffffffu, s1b, 2);
        s2b += __shfl_xor_sync(0xffffffffu, s2b, 1); s2b += __shfl_xor_sync(0xffffffffu, s2b, 2);
        const float mua = s1a * (1.f/128.f);
        const float rsa = rsqrtf(fmaxf(s2a * (1.f/128.f) - mua*mua, 0.f) + EPS);
        const float mub = s1b * (1.f/128.f);
        const float rsb = rsqrtf(fmaxf(s2b * (1.f/128.f) - mub*mub, 0.f) + EPS);

        // ---- A2 = LN2(xm) -> fp8 into s8 region (dead after w2 GEMM) ----
        #pragma unroll
        for (int nb = 0; nb < 16; ++nb) {
            int n0 = 8 * nb + 2 * q;
            float2 p0 = elnp[n0], p1 = elnp[n0 + 1];
            float2 va = *(const float2*)(xms + (m0 + r)     * 132 + n0);
            float2 vb = *(const float2*)(xms + (m0 + r + 8) * 132 + n0);
            *(uint16_t*)(sm + KB_S8 + (m0 + r)     * SA8 + n0) =
                pack_e4m3x2((va.x-mua)*rsa*p0.x+p0.y, (va.y-mua)*rsa*p1.x+p1.y);
            *(uint16_t*)(sm + KB_S8 + (m0 + r + 8) * SA8 + n0) =
                pack_e4m3x2((vb.x-mub)*rsb*p0.x+p0.y, (vb.y-mub)*rsb*p1.x+p1.y);
        }
        __syncwarp();

        // ---- GEMM wf1 fp8 (paired, 2 x n128 passes); gate -> bf16 atile ----
        #pragma unroll 1
        for (int half = 0; half < 2; ++half) {
            float acc2[16][4];
            #pragma unroll
            for (int nb = 0; nb < 16; ++nb)
                { acc2[nb][0]=0.f; acc2[nb][1]=0.f; acc2[nb][2]=0.f; acc2[nb][3]=0.f; }
            #pragma unroll 2
            for (int ks = 0; ks < 4; ++ks) {
                int kb = 32 * ks + 4 * q;
                uint32_t a0 = *(const uint32_t*)(a8r + kb);
                uint32_t a1 = *(const uint32_t*)(a8r + 8 * SA8 + kb);
                uint32_t a2 = *(const uint32_t*)(a8r + kb + 16);
                uint32_t a3 = *(const uint32_t*)(a8r + 8 * SA8 + kb + 16);
                const uint4* fb = (const uint4*)(sm + KB_FWF1) + (ks * 2 + half) * 256 + lane;
                #pragma unroll
                for (int nbp = 0; nbp < 8; ++nbp) {
                    uint4 b = fb[nbp * 32];
                    mma_fp8(acc2[2*nbp],   a0, a1, a2, a3, b.x, b.y);
                    mma_fp8(acc2[2*nbp+1], a0, a1, a2, a3, b.z, b.w);
                }
            }
            #pragma unroll
            for (int nb = 0; nb < 16; ++nb) {
                int nbg = half * 16 + nb;
                int n0 = 8 * nbg + 2 * q, j = 4 * nbg + q;
                float e0 = ebfp[n0], e1 = ebfp[n0 + 1];
                float lo = (acc2[nb][0]*IVF1 + e0) * (acc2[nb][1]*IVF1 + e1);
                float hi = (acc2[nb][2]*IVF1 + e0) * (acc2[nb][3]*IVF1 + e1);
                *(__nv_bfloat16*)(sm + (m0 + r)     * SA + j * 2) = __float2bfloat16(lo);
                *(__nv_bfloat16*)(sm + (m0 + r + 8) * SA + j * 2) = __float2bfloat16(hi);
            }
        }
        __syncwarp();

        // ---- GEMM wf2 bf16 (n128), frags via LDG.128 ----
        float acc3[16][4];
        #pragma unroll
        for (int nb = 0; nb < 16; ++nb)
            { acc3[nb][0]=0.f; acc3[nb][1]=0.f; acc3[nb][2]=0.f; acc3[nb][3]=0.f; }
        #pragma unroll 2
        for (int ks = 0; ks < 8; ++ks) {
            int kb = 32 * ks + 4 * q;
            uint32_t a0 = *(const uint32_t*)(ar0 + kb);
            uint32_t a1 = *(const uint32_t*)(ar0 + 8 * SA + kb);
            uint32_t a2 = *(const uint32_t*)(ar0 + kb + 16);
            uint32_t a3 = *(const uint32_t*)(ar0 + 8 * SA + kb + 16);
            const uint4* fb = (const uint4*)g_fwf2 + ks * 256 + lane;
            #pragma unroll
            for (int nbp = 0; nbp < 8; ++nbp) {
                uint4 b = __ldg(fb + nbp * 32);
                mma_bf16(acc3[2*nbp],   a0, a1, a2, a3, b.x, b.y);
                mma_bf16(acc3[2*nbp+1], a0, a1, a2, a3, b.z, b.w);
            }
        }

        // ---- prefetch next tile's s (s8 region dead after wf1 GEMM) ----
        if (it < 15) { prefetch_s(tile + 18); CP_COMMIT(); }

        // ---- out = xm + gamma*(d+bf2) ----
        float* or0 = out + ((size_t)(tile * 128 + m0 + r)) * 128;
        float* or8 = or0 + (size_t)8 * 128;
        #pragma unroll
        for (int nb = 0; nb < 16; ++nb) {
            int n0 = 8 * nb + 2 * q;
            float2 g0 = egap[n0], g1 = egap[n0 + 1];
            float2 va = *(const float2*)(xms + (m0 + r)     * 132 + n0);
            float2 vb = *(const float2*)(xms + (m0 + r + 8) * 132 + n0);
            *(float2*)(or0 + n0) = make_float2(va.x + acc3[nb][0]*g0.x + g0.y,
                                               va.y + acc3[nb][1]*g1.x + g1.y);
            *(float2*)(or8 + n0) = make_float2(vb.x + acc3[nb][2]*g0.x + g0.y,
                                               vb.y + acc3[nb][3]*g1.x + g1.y);
        }

        // ---- prefetch next tile's x (xm region dead now) ----
        if (it < 15) { prefetch_x(tile + 18); CP_COMMIT(); }
        __syncwarp();
    }
}

// =====================================================================
// launch
// =====================================================================
extern "C" void kernel_launch(void* const* d_in, const int* in_sizes, int n_in,
                              void* d_out, int out_size)
{
    (void)in_sizes; (void)n_in; (void)out_size;
    const float* x     = (const float*)d_in[0];
    const float* ln1s  = (const float*)d_in[1];
    const float* ln1b  = (const float*)d_in[2];
    const float* w1    = (const float*)d_in[3];
    const float* b1    = (const float*)d_in[4];
    const float* wdw   = (const float*)d_in[5];
    const float* bdw   = (const float*)d_in[6];
    const float* wse   = (const float*)d_in[7];
    const float* bse   = (const float*)d_in[8];
    const float* w2    = (const float*)d_in[9];
    const float* b2    = (const float*)d_in[10];
    const float* ln2s  = (const float*)d_in[11];
    const float* ln2b  = (const float*)d_in[12];
    const float* wf1   = (const float*)d_in[13];
    const float* bf1   = (const float*)d_in[14];
    const float* wf2   = (const float*)d_in[15];
    const float* bf2   = (const float*)d_in[16];
    const float* beta  = (const float*)d_in[17];
    const float* gamma = (const float*)d_in[18];
    float* out = (float*)d_out;

    cudaFuncSetAttribute(kA_spatial, cudaFuncAttributeMaxDynamicSharedMemorySize, KA_SMEM);
    cudaFuncSetAttribute(kB_ffn,     cudaFuncAttributeMaxDynamicSharedMemorySize, KB_SMEM);

    k0_frags<<<64, 256>>>(w1, w2, wf1, wf2);
    kA_spatial<<<GRID_A, 256, KA_SMEM>>>(x, ln1s, ln1b, b1, wdw, bdw);
    k2_se<<<B_, 512>>>(wse, bse);
    kB_ffn<<<GRID_B, 256, KB_SMEM>>>(x, b2, beta, ln2s, ln2b, bf1, bf2, gamma, out);
}